// round 1
// baseline (speedup 1.0000x reference)
#include <cuda_runtime.h>
#include <math_constants.h>
#include <cstdint>

// Problem constants
#define Bsz 2
#define Sq  2048
#define Dm  2048
#define Hh  16
#define Ll  512
#define HDm 128
#define Mrows (Bsz*Sq)      // 4096

// ---------------------------------------------------------------------------
// Scratch (static device globals — no runtime allocation allowed)
// ---------------------------------------------------------------------------
__device__ float g_qlat [(size_t)Mrows * Ll];      //  8 MB
__device__ float g_q    [(size_t)Mrows * Dm];      // 32 MB
__device__ float g_kvlat[(size_t)Mrows * Ll];      //  8 MB
__device__ float g_kv   [(size_t)Mrows * 2 * Dm];  // 64 MB
__device__ float g_attn [(size_t)Mrows * Dm];      // 32 MB

// ---------------------------------------------------------------------------
// SGEMM with bias: C[M,N] = A[M,K] @ B[K,N] + bias[N]
// Classic 128x128 tile, BK=8, 256 threads, 8x8 per-thread microtile.
// Requires M%128==0, N%128==0, K%8==0 (all shapes here satisfy this).
// ---------------------------------------------------------------------------
__global__ __launch_bounds__(256) void sgemm_bias(
    int M, int N, int K,
    const float* __restrict__ A,
    const float* __restrict__ B,
    const float* __restrict__ bias,
    float* __restrict__ C)
{
    constexpr int BM = 128, BN = 128, BK = 8, TM = 8, TN = 8;
    __shared__ float As[BK][BM];
    __shared__ float Bs[BK][BN];

    const int bx = blockIdx.x, by = blockIdx.y;
    const int tid = threadIdx.x;
    const int tx = tid & 15;        // 0..15 (col group)
    const int ty = tid >> 4;        // 0..15 (row group)

    const float* Ab = A + (size_t)by * BM * K;
    const float* Bb = B + (size_t)bx * BN;

    const int aRow = tid >> 1;            // 0..127
    const int aCol = (tid & 1) * 4;       // 0 or 4
    const int bRow = tid >> 5;            // 0..7
    const int bCol = (tid & 31) * 4;      // 0..124

    float acc[TM][TN];
    #pragma unroll
    for (int i = 0; i < TM; i++)
        #pragma unroll
        for (int j = 0; j < TN; j++) acc[i][j] = 0.f;

    for (int k0 = 0; k0 < K; k0 += BK) {
        float4 a4 = *(const float4*)(Ab + (size_t)aRow * K + k0 + aCol);
        As[aCol + 0][aRow] = a4.x;
        As[aCol + 1][aRow] = a4.y;
        As[aCol + 2][aRow] = a4.z;
        As[aCol + 3][aRow] = a4.w;
        float4 b4 = *(const float4*)(Bb + (size_t)(k0 + bRow) * N + bCol);
        *(float4*)&Bs[bRow][bCol] = b4;
        __syncthreads();

        #pragma unroll
        for (int k = 0; k < BK; k++) {
            float ra[TM], rb[TN];
            #pragma unroll
            for (int i = 0; i < TM; i++) ra[i] = As[k][ty * TM + i];
            #pragma unroll
            for (int j = 0; j < TN; j++) rb[j] = Bs[k][tx * TN + j];
            #pragma unroll
            for (int i = 0; i < TM; i++)
                #pragma unroll
                for (int j = 0; j < TN; j++)
                    acc[i][j] += ra[i] * rb[j];
        }
        __syncthreads();
    }

    const int colBase = bx * BN + tx * TN;
    #pragma unroll
    for (int i = 0; i < TM; i++) {
        size_t row = (size_t)by * BM + ty * TM + i;
        float* Cr = C + row * N + colBase;
        #pragma unroll
        for (int j0 = 0; j0 < TN; j0 += 4) {
            float4 o;
            o.x = acc[i][j0 + 0] + bias[colBase + j0 + 0];
            o.y = acc[i][j0 + 1] + bias[colBase + j0 + 1];
            o.z = acc[i][j0 + 2] + bias[colBase + j0 + 2];
            o.w = acc[i][j0 + 3] + bias[colBase + j0 + 3];
            *(float4*)(Cr + j0) = o;
        }
    }
}

// ---------------------------------------------------------------------------
// LayerNorm over last dim (512), in place. One block (256 threads) per row.
// ---------------------------------------------------------------------------
__global__ __launch_bounds__(256) void ln512(
    float* __restrict__ x,
    const float* __restrict__ g,
    const float* __restrict__ b)
{
    const int row = blockIdx.x;
    float* xr = x + (size_t)row * Ll;
    const int tid = threadIdx.x;

    float v0 = xr[tid];
    float v1 = xr[tid + 256];
    float s  = v0 + v1;
    float sq = v0 * v0 + v1 * v1;

    #pragma unroll
    for (int o = 16; o > 0; o >>= 1) {
        s  += __shfl_xor_sync(0xffffffffu, s,  o);
        sq += __shfl_xor_sync(0xffffffffu, sq, o);
    }
    __shared__ float ss[8], ssq[8];
    __shared__ float mean_sh, inv_sh;
    const int w = tid >> 5;
    if ((tid & 31) == 0) { ss[w] = s; ssq[w] = sq; }
    __syncthreads();
    if (tid == 0) {
        float S = 0.f, SQ = 0.f;
        #pragma unroll
        for (int i = 0; i < 8; i++) { S += ss[i]; SQ += ssq[i]; }
        float m = S * (1.f / Ll);
        float var = SQ * (1.f / Ll) - m * m;
        mean_sh = m;
        inv_sh = rsqrtf(var + 1e-5f);
    }
    __syncthreads();
    const float m = mean_sh, inv = inv_sh;
    xr[tid]       = (v0 - m) * inv * g[tid]       + b[tid];
    xr[tid + 256] = (v1 - m) * inv * g[tid + 256] + b[tid + 256];
}

// ---------------------------------------------------------------------------
// Flash-style causal attention per (b,h). BM=BN=32, 128 threads.
// q:   [B*S, D]   (head h at cols h*128 .. h*128+127)
// kv:  [B*S, 2D]  (K at cols h*128.., V at cols D + h*128..)
// out: [B*S, D]   same head layout as q
// Thread layout: r = tid/4 (query row in tile), qd = tid%4 (quad member).
// Each thread owns output dims d = qd + 4*j (j = 0..31).
// ---------------------------------------------------------------------------
#define ATT_QS_STRIDE 130
#define ATT_PS_STRIDE 33
#define ATT_SMEM ((3 * 32 * ATT_QS_STRIDE + 32 * ATT_PS_STRIDE) * 4)

__global__ __launch_bounds__(128) void attn_kernel(
    const float* __restrict__ q,
    const float* __restrict__ kv,
    const unsigned char* __restrict__ mask,
    float* __restrict__ out)
{
    const int bh = blockIdx.y;
    const int b = bh / Hh, h = bh % Hh;
    const int q0 = blockIdx.x * 32;

    const float* Qp = q  + (size_t)b * Sq * Dm       + (size_t)h * HDm;
    const float* Kp = kv + (size_t)b * Sq * (2 * Dm) + (size_t)h * HDm;
    const float* Vp = Kp + Dm;
    const unsigned char* mp = mask + (size_t)b * Sq;

    extern __shared__ float sm[];
    float* Qs = sm;                         // 32 x 130
    float* Ks = sm + 32 * ATT_QS_STRIDE;    // 32 x 130
    float* Vs = sm + 64 * ATT_QS_STRIDE;    // 32 x 130
    float* Ps = sm + 96 * ATT_QS_STRIDE;    // 32 x 33

    const int tid = threadIdx.x;
    const int r  = tid >> 2;
    const int qd = tid & 3;
    const int qrow = q0 + r;

    // Load Q tile (32 x 128), coalesced float4
    for (int i = tid; i < 1024; i += 128) {
        int row = i >> 5, c4 = (i & 31) << 2;
        float4 v = *(const float4*)(Qp + (size_t)(q0 + row) * Dm + c4);
        float* dst = Qs + row * ATT_QS_STRIDE + c4;
        dst[0] = v.x; dst[1] = v.y; dst[2] = v.z; dst[3] = v.w;
    }

    float m_i = -CUDART_INF_F, l_i = 0.f;
    float acc[32];
    #pragma unroll
    for (int j = 0; j < 32; j++) acc[j] = 0.f;
    const float scale = 0.08838834764831845f;   // 1/sqrt(128)

    for (int k0 = 0; k0 < q0 + 32; k0 += 32) {
        __syncthreads();   // previous tile fully consumed; Q store visible
        for (int i = tid; i < 1024; i += 128) {
            int row = i >> 5, c4 = (i & 31) << 2;
            size_t base = (size_t)(k0 + row) * (2 * Dm) + c4;
            float4 k4 = *(const float4*)(Kp + base);
            float* kd = Ks + row * ATT_QS_STRIDE + c4;
            kd[0] = k4.x; kd[1] = k4.y; kd[2] = k4.z; kd[3] = k4.w;
            float4 v4 = *(const float4*)(Vp + base);
            float* vd = Vs + row * ATT_QS_STRIDE + c4;
            vd[0] = v4.x; vd[1] = v4.y; vd[2] = v4.z; vd[3] = v4.w;
        }
        __syncthreads();

        // Scores for keys (qd + 4*kk), kk = 0..7
        float s[8];
        #pragma unroll
        for (int kk = 0; kk < 8; kk++) s[kk] = 0.f;
        #pragma unroll 4
        for (int d = 0; d < HDm; d++) {
            float qv = Qs[r * ATT_QS_STRIDE + d];
            #pragma unroll
            for (int kk = 0; kk < 8; kk++)
                s[kk] += qv * Ks[(qd + 4 * kk) * ATT_QS_STRIDE + d];
        }

        float mt = -CUDART_INF_F;
        #pragma unroll
        for (int kk = 0; kk < 8; kk++) {
            int kg = k0 + qd + 4 * kk;
            if (kg > qrow || mp[kg]) s[kk] = -CUDART_INF_F;
            else s[kk] *= scale;
            mt = fmaxf(mt, s[kk]);
        }
        // row-max across quad
        mt = fmaxf(mt, __shfl_xor_sync(0xffffffffu, mt, 1));
        mt = fmaxf(mt, __shfl_xor_sync(0xffffffffu, mt, 2));
        float m_new = fmaxf(m_i, mt);
        float corr = (m_new == -CUDART_INF_F) ? 1.f : __expf(m_i - m_new);

        float psum = 0.f;
        #pragma unroll
        for (int kk = 0; kk < 8; kk++) {
            float p = (s[kk] == -CUDART_INF_F) ? 0.f : __expf(s[kk] - m_new);
            Ps[r * ATT_PS_STRIDE + qd + 4 * kk] = p;
            psum += p;
        }
        psum += __shfl_xor_sync(0xffffffffu, psum, 1);
        psum += __shfl_xor_sync(0xffffffffu, psum, 2);
        l_i = l_i * corr + psum;
        m_i = m_new;

        #pragma unroll
        for (int j = 0; j < 32; j++) acc[j] *= corr;
        __syncwarp();   // Ps row r written by this quad (same warp)

        #pragma unroll 4
        for (int key = 0; key < 32; key++) {
            float p = Ps[r * ATT_PS_STRIDE + key];
            #pragma unroll
            for (int j = 0; j < 32; j++)
                acc[j] += p * Vs[key * ATT_QS_STRIDE + qd + 4 * j];
        }
    }

    const float invl = (l_i > 0.f) ? (1.f / l_i) : 0.f;
    float* op = out + (size_t)(b * Sq + qrow) * Dm + (size_t)h * HDm;
    #pragma unroll
    for (int j = 0; j < 32; j++)
        op[qd + 4 * j] = acc[j] * invl;
}

// ---------------------------------------------------------------------------
// Launch
// ---------------------------------------------------------------------------
extern "C" void kernel_launch(void* const* d_in, const int* in_sizes, int n_in,
                              void* d_out, int out_size)
{
    const float*         x        = (const float*)d_in[0];
    const unsigned char* mask     = (const unsigned char*)d_in[1];
    const float*         wq_down  = (const float*)d_in[2];
    const float*         bq_down  = (const float*)d_in[3];
    const float*         gq_ln    = (const float*)d_in[4];
    const float*         bq_ln    = (const float*)d_in[5];
    const float*         wq_up    = (const float*)d_in[6];
    const float*         bq_up    = (const float*)d_in[7];
    const float*         wkv_down = (const float*)d_in[8];
    const float*         bkv_down = (const float*)d_in[9];
    const float*         gkv_ln   = (const float*)d_in[10];
    const float*         bkv_ln   = (const float*)d_in[11];
    const float*         wkv_up   = (const float*)d_in[12];
    const float*         bkv_up   = (const float*)d_in[13];
    const float*         w_out    = (const float*)d_in[14];
    const float*         b_out    = (const float*)d_in[15];
    float* out = (float*)d_out;

    float *qlat, *qb, *kvlat, *kvb, *attnb;
    cudaGetSymbolAddress((void**)&qlat,  g_qlat);
    cudaGetSymbolAddress((void**)&qb,    g_q);
    cudaGetSymbolAddress((void**)&kvlat, g_kvlat);
    cudaGetSymbolAddress((void**)&kvb,   g_kv);
    cudaGetSymbolAddress((void**)&attnb, g_attn);

    cudaFuncSetAttribute(attn_kernel,
                         cudaFuncAttributeMaxDynamicSharedMemorySize, ATT_SMEM);

    // Q path: down-proj -> LN -> up-proj
    sgemm_bias<<<dim3(Ll / 128, Mrows / 128), 256>>>(Mrows, Ll, Dm, x, wq_down, bq_down, qlat);
    ln512<<<Mrows, 256>>>(qlat, gq_ln, bq_ln);
    sgemm_bias<<<dim3(Dm / 128, Mrows / 128), 256>>>(Mrows, Dm, Ll, qlat, wq_up, bq_up, qb);

    // KV path: down-proj -> LN -> up-proj (k | v concatenated)
    sgemm_bias<<<dim3(Ll / 128, Mrows / 128), 256>>>(Mrows, Ll, Dm, x, wkv_down, bkv_down, kvlat);
    ln512<<<Mrows, 256>>>(kvlat, gkv_ln, bkv_ln);
    sgemm_bias<<<dim3(2 * Dm / 128, Mrows / 128), 256>>>(Mrows, 2 * Dm, Ll, kvlat, wkv_up, bkv_up, kvb);

    // Causal multi-head attention (flash-style)
    attn_kernel<<<dim3(Sq / 32, Bsz * Hh), 128, ATT_SMEM>>>(qb, kvb, mask, attnb);

    // Output projection
    sgemm_bias<<<dim3(Dm / 128, Mrows / 128), 256>>>(Mrows, Dm, Dm, attnb, w_out, b_out, out);
}

// round 3
// speedup vs baseline: 1.1778x; 1.1778x over previous
#include <cuda_runtime.h>
#include <math_constants.h>
#include <cstdint>

// Problem constants
#define Bsz 2
#define Sq  2048
#define Dm  2048
#define Hh  16
#define Ll  512
#define HDm 128
#define Mrows (Bsz*Sq)      // 4096

// ---------------------------------------------------------------------------
// Scratch (static device globals — no runtime allocation allowed)
// ---------------------------------------------------------------------------
__device__ float g_qlat [(size_t)Mrows * Ll];       //  8 MB
__device__ float g_q    [(size_t)Mrows * Dm];       // 32 MB
__device__ float g_kvlat[(size_t)Mrows * Ll];       //  8 MB
__device__ float g_kv   [(size_t)Mrows * 2 * Dm];   // 64 MB
__device__ float g_attn [(size_t)Mrows * Dm];       // 32 MB

// ---------------------------------------------------------------------------
// Helpers
// ---------------------------------------------------------------------------
__device__ __forceinline__ uint32_t smem_u32(const void* p) {
    uint32_t a;
    asm("{ .reg .u64 t; cvta.to.shared.u64 t, %1; cvt.u32.u64 %0, t; }"
        : "=r"(a) : "l"(p));
    return a;
}
__device__ __forceinline__ void cp16(uint32_t dst, const void* src) {
    asm volatile("cp.async.cg.shared.global [%0], [%1], 16;"
                 :: "r"(dst), "l"(src) : "memory");
}
__device__ __forceinline__ float rna_tf32(float a) {
    float r;
    asm("cvt.rna.tf32.f32 %0, %1;" : "=f"(r) : "f"(a));
    return r;
}
// mma.sync m16n8k8 tf32 (baseline PTX since sm_80 — compiles on sm_103)
__device__ __forceinline__ void mma_tf32(
    float c[4], uint32_t a0, uint32_t a1, uint32_t a2, uint32_t a3,
    uint32_t b0, uint32_t b1)
{
    asm volatile(
        "mma.sync.aligned.m16n8k8.row.col.f32.tf32.tf32.f32 "
        "{%0,%1,%2,%3}, {%4,%5,%6,%7}, {%8,%9}, {%0,%1,%2,%3};"
        : "+f"(c[0]), "+f"(c[1]), "+f"(c[2]), "+f"(c[3])
        : "r"(a0), "r"(a1), "r"(a2), "r"(a3), "r"(b0), "r"(b1));
}

// ---------------------------------------------------------------------------
// 3xTF32 GEMM via mma.sync: C[M,N] = A[M,K] @ W[K,N] + bias[N]
// CTA tile 128x128, BK=16, 256 threads (8 warps, warp tile 64x32).
// A in smem [m][k] stride 20; W in smem [k][n] stride 136 (conflict-free).
// Requires M%128==0, N%128==0, K%16==0.
// ---------------------------------------------------------------------------
#define ASTR 20
#define BSTR 136

__global__ __launch_bounds__(256) void gemm_mma3(
    int M, int N, int K,
    const float* __restrict__ A,
    const float* __restrict__ W,
    const float* __restrict__ bias,
    float* __restrict__ C)
{
    __shared__ __align__(16) float As[2][128 * ASTR];
    __shared__ __align__(16) float Bs[2][16 * BSTR];

    const int tid = threadIdx.x;
    const int wid = tid >> 5, lid = tid & 31;
    const int g = lid >> 2, lq = lid & 3;       // fragment row-group / quad lane
    const int m0 = blockIdx.y * 128, n0 = blockIdx.x * 128;
    const int warp_m = (wid & 1) * 64;          // 2 warps along M
    const int warp_n = (wid >> 1) * 32;         // 4 warps along N
    const int nc = K >> 4;

    const uint32_t sA0 = smem_u32(&As[0][0]);
    const uint32_t sB0 = smem_u32(&Bs[0][0]);

    float acc[4][4][4];
    #pragma unroll
    for (int mt = 0; mt < 4; mt++)
        #pragma unroll
        for (int nt = 0; nt < 4; nt++)
            #pragma unroll
            for (int e = 0; e < 4; e++) acc[mt][nt][e] = 0.f;

    // --- async tile loader: A 128x16, B 16x128 ---
    auto load_tile = [&](int c, int stg) {
        const int k0 = c << 4;
        const uint32_t sa = sA0 + stg * (128 * ASTR * 4);
        const uint32_t sb = sB0 + stg * (16 * BSTR * 4);
        // A: 512 float4 chunks; thread handles 2
        #pragma unroll
        for (int t = 0; t < 2; t++) {
            int idx = tid + t * 256;
            int m = idx >> 2, k4 = idx & 3;
            cp16(sa + (m * ASTR + k4 * 4) * 4,
                 A + (size_t)(m0 + m) * K + k0 + k4 * 4);
        }
        // B: 512 float4 chunks; thread handles 2
        #pragma unroll
        for (int t = 0; t < 2; t++) {
            int idx = tid + t * 256;
            int k = idx >> 5, nq = idx & 31;
            cp16(sb + (k * BSTR + nq * 4) * 4,
                 W + (size_t)(k0 + k) * N + n0 + nq * 4);
        }
        asm volatile("cp.async.commit_group;" ::: "memory");
    };

    load_tile(0, 0);
    if (nc > 1) load_tile(1, 1);

    for (int c = 0; c < nc; ++c) {
        const int cur = c & 1;
        if (c + 1 < nc) { asm volatile("cp.async.wait_group 1;" ::: "memory"); }
        else            { asm volatile("cp.async.wait_group 0;" ::: "memory"); }
        __syncthreads();

        const float* as = &As[cur][0];
        const float* bs = &Bs[cur][0];

        #pragma unroll
        for (int ks = 0; ks < 2; ks++) {
            const int kb = ks * 8;
            // ---- load + split A fragments (4 m-tiles) ----
            uint32_t Ah[4][4], Al[4][4];
            #pragma unroll
            for (int mt = 0; mt < 4; mt++) {
                const int rbase = warp_m + mt * 16 + g;
                #pragma unroll
                for (int e = 0; e < 4; e++) {
                    const int row = rbase + (e & 1) * 8;
                    const int col = kb + lq + (e >> 1) * 4;
                    float a = as[row * ASTR + col];
                    float h = rna_tf32(a);
                    Ah[mt][e] = __float_as_uint(h);
                    Al[mt][e] = __float_as_uint(rna_tf32(a - h));
                }
            }
            // ---- load + split B fragments (4 n-tiles) ----
            uint32_t Bh[4][2], Bl[4][2];
            #pragma unroll
            for (int nt = 0; nt < 4; nt++) {
                const int nn = warp_n + nt * 8 + g;
                #pragma unroll
                for (int e = 0; e < 2; e++) {
                    const int kk = kb + lq + e * 4;
                    float b = bs[kk * BSTR + nn];
                    float h = rna_tf32(b);
                    Bh[nt][e] = __float_as_uint(h);
                    Bl[nt][e] = __float_as_uint(rna_tf32(b - h));
                }
            }
            // ---- 3xTF32 mmas ----
            #pragma unroll
            for (int mt = 0; mt < 4; mt++)
                #pragma unroll
                for (int nt = 0; nt < 4; nt++) {
                    mma_tf32(acc[mt][nt], Ah[mt][0], Ah[mt][1], Ah[mt][2], Ah[mt][3],
                             Bl[nt][0], Bl[nt][1]);
                    mma_tf32(acc[mt][nt], Al[mt][0], Al[mt][1], Al[mt][2], Al[mt][3],
                             Bh[nt][0], Bh[nt][1]);
                    mma_tf32(acc[mt][nt], Ah[mt][0], Ah[mt][1], Ah[mt][2], Ah[mt][3],
                             Bh[nt][0], Bh[nt][1]);
                }
        }
        __syncthreads();
        if (c + 2 < nc) load_tile(c + 2, cur);
    }

    // ---- epilogue: accum + bias -> C (float2 stores, quad-contiguous 32B) ----
    #pragma unroll
    for (int mt = 0; mt < 4; mt++) {
        const int r0 = m0 + warp_m + mt * 16 + g;
        #pragma unroll
        for (int nt = 0; nt < 4; nt++) {
            const int col = n0 + warp_n + nt * 8 + lq * 2;
            const float2 b2 = *(const float2*)(bias + col);
            float2 o;
            o.x = acc[mt][nt][0] + b2.x;
            o.y = acc[mt][nt][1] + b2.y;
            *(float2*)(C + (size_t)r0 * N + col) = o;
            o.x = acc[mt][nt][2] + b2.x;
            o.y = acc[mt][nt][3] + b2.y;
            *(float2*)(C + (size_t)(r0 + 8) * N + col) = o;
        }
    }
}

// ---------------------------------------------------------------------------
// LayerNorm over last dim (512), in place. One block (256 threads) per row.
// ---------------------------------------------------------------------------
__global__ __launch_bounds__(256) void ln512(
    float* __restrict__ x,
    const float* __restrict__ g,
    const float* __restrict__ b)
{
    const int row = blockIdx.x;
    float* xr = x + (size_t)row * Ll;
    const int tid = threadIdx.x;

    float v0 = xr[tid];
    float v1 = xr[tid + 256];
    float s  = v0 + v1;
    float sq = v0 * v0 + v1 * v1;

    #pragma unroll
    for (int o = 16; o > 0; o >>= 1) {
        s  += __shfl_xor_sync(0xffffffffu, s,  o);
        sq += __shfl_xor_sync(0xffffffffu, sq, o);
    }
    __shared__ float ss[8], ssq[8];
    __shared__ float mean_sh, inv_sh;
    const int w = tid >> 5;
    if ((tid & 31) == 0) { ss[w] = s; ssq[w] = sq; }
    __syncthreads();
    if (tid == 0) {
        float S = 0.f, SQ = 0.f;
        #pragma unroll
        for (int i = 0; i < 8; i++) { S += ss[i]; SQ += ssq[i]; }
        float m = S * (1.f / Ll);
        float var = SQ * (1.f / Ll) - m * m;
        mean_sh = m;
        inv_sh = rsqrtf(var + 1e-5f);
    }
    __syncthreads();
    const float m = mean_sh, inv = inv_sh;
    xr[tid]       = (v0 - m) * inv * g[tid]       + b[tid];
    xr[tid + 256] = (v1 - m) * inv * g[tid + 256] + b[tid + 256];
}

// ---------------------------------------------------------------------------
// Flash-style causal attention per (b,h). BM=BN=32, 128 threads. (unchanged)
// ---------------------------------------------------------------------------
#define ATT_QS_STRIDE 130
#define ATT_PS_STRIDE 33
#define ATT_SMEM ((3 * 32 * ATT_QS_STRIDE + 32 * ATT_PS_STRIDE) * 4)

__global__ __launch_bounds__(128) void attn_kernel(
    const float* __restrict__ q,
    const float* __restrict__ kv,
    const unsigned char* __restrict__ mask,
    float* __restrict__ out)
{
    const int bh = blockIdx.y;
    const int b = bh / Hh, h = bh % Hh;
    const int q0 = blockIdx.x * 32;

    const float* Qp = q  + (size_t)b * Sq * Dm       + (size_t)h * HDm;
    const float* Kp = kv + (size_t)b * Sq * (2 * Dm) + (size_t)h * HDm;
    const float* Vp = Kp + Dm;
    const unsigned char* mp = mask + (size_t)b * Sq;

    extern __shared__ float smf[];
    float* Qs = smf;
    float* Ks = smf + 32 * ATT_QS_STRIDE;
    float* Vs = smf + 64 * ATT_QS_STRIDE;
    float* Ps = smf + 96 * ATT_QS_STRIDE;

    const int tid = threadIdx.x;
    const int r  = tid >> 2;
    const int qd = tid & 3;
    const int qrow = q0 + r;

    for (int i = tid; i < 1024; i += 128) {
        int row = i >> 5, c4 = (i & 31) << 2;
        float4 v = *(const float4*)(Qp + (size_t)(q0 + row) * Dm + c4);
        float* dst = Qs + row * ATT_QS_STRIDE + c4;
        dst[0] = v.x; dst[1] = v.y; dst[2] = v.z; dst[3] = v.w;
    }

    float m_i = -CUDART_INF_F, l_i = 0.f;
    float acc[32];
    #pragma unroll
    for (int j = 0; j < 32; j++) acc[j] = 0.f;
    const float scale = 0.08838834764831845f;   // 1/sqrt(128)

    for (int k0 = 0; k0 < q0 + 32; k0 += 32) {
        __syncthreads();
        for (int i = tid; i < 1024; i += 128) {
            int row = i >> 5, c4 = (i & 31) << 2;
            size_t base = (size_t)(k0 + row) * (2 * Dm) + c4;
            float4 k4 = *(const float4*)(Kp + base);
            float* kd = Ks + row * ATT_QS_STRIDE + c4;
            kd[0] = k4.x; kd[1] = k4.y; kd[2] = k4.z; kd[3] = k4.w;
            float4 v4 = *(const float4*)(Vp + base);
            float* vd = Vs + row * ATT_QS_STRIDE + c4;
            vd[0] = v4.x; vd[1] = v4.y; vd[2] = v4.z; vd[3] = v4.w;
        }
        __syncthreads();

        float s[8];
        #pragma unroll
        for (int kk = 0; kk < 8; kk++) s[kk] = 0.f;
        #pragma unroll 4
        for (int d = 0; d < HDm; d++) {
            float qv = Qs[r * ATT_QS_STRIDE + d];
            #pragma unroll
            for (int kk = 0; kk < 8; kk++)
                s[kk] += qv * Ks[(qd + 4 * kk) * ATT_QS_STRIDE + d];
        }

        float mt = -CUDART_INF_F;
        #pragma unroll
        for (int kk = 0; kk < 8; kk++) {
            int kg = k0 + qd + 4 * kk;
            if (kg > qrow || mp[kg]) s[kk] = -CUDART_INF_F;
            else s[kk] *= scale;
            mt = fmaxf(mt, s[kk]);
        }
        mt = fmaxf(mt, __shfl_xor_sync(0xffffffffu, mt, 1));
        mt = fmaxf(mt, __shfl_xor_sync(0xffffffffu, mt, 2));
        float m_new = fmaxf(m_i, mt);
        float corr = (m_new == -CUDART_INF_F) ? 1.f : __expf(m_i - m_new);

        float psum = 0.f;
        #pragma unroll
        for (int kk = 0; kk < 8; kk++) {
            float p = (s[kk] == -CUDART_INF_F) ? 0.f : __expf(s[kk] - m_new);
            Ps[r * ATT_PS_STRIDE + qd + 4 * kk] = p;
            psum += p;
        }
        psum += __shfl_xor_sync(0xffffffffu, psum, 1);
        psum += __shfl_xor_sync(0xffffffffu, psum, 2);
        l_i = l_i * corr + psum;
        m_i = m_new;

        #pragma unroll
        for (int j = 0; j < 32; j++) acc[j] *= corr;
        __syncwarp();

        #pragma unroll 4
        for (int key = 0; key < 32; key++) {
            float p = Ps[r * ATT_PS_STRIDE + key];
            #pragma unroll
            for (int j = 0; j < 32; j++)
                acc[j] += p * Vs[key * ATT_QS_STRIDE + qd + 4 * j];
        }
    }

    const float invl = (l_i > 0.f) ? (1.f / l_i) : 0.f;
    float* op = out + (size_t)(b * Sq + qrow) * Dm + (size_t)h * HDm;
    #pragma unroll
    for (int j = 0; j < 32; j++)
        op[qd + 4 * j] = acc[j] * invl;
}

// ---------------------------------------------------------------------------
// Launch
// ---------------------------------------------------------------------------
extern "C" void kernel_launch(void* const* d_in, const int* in_sizes, int n_in,
                              void* d_out, int out_size)
{
    const float*         x        = (const float*)d_in[0];
    const unsigned char* mask     = (const unsigned char*)d_in[1];
    const float*         wq_down  = (const float*)d_in[2];
    const float*         bq_down  = (const float*)d_in[3];
    const float*         gq_ln    = (const float*)d_in[4];
    const float*         bq_ln    = (const float*)d_in[5];
    const float*         wq_up    = (const float*)d_in[6];
    const float*         bq_up    = (const float*)d_in[7];
    const float*         wkv_down = (const float*)d_in[8];
    const float*         bkv_down = (const float*)d_in[9];
    const float*         gkv_ln   = (const float*)d_in[10];
    const float*         bkv_ln   = (const float*)d_in[11];
    const float*         wkv_up   = (const float*)d_in[12];
    const float*         bkv_up   = (const float*)d_in[13];
    const float*         w_out    = (const float*)d_in[14];
    const float*         b_out    = (const float*)d_in[15];
    float* out = (float*)d_out;

    float *qlat, *qb, *kvlat, *kvb, *attnb;
    cudaGetSymbolAddress((void**)&qlat,  g_qlat);
    cudaGetSymbolAddress((void**)&qb,    g_q);
    cudaGetSymbolAddress((void**)&kvlat, g_kvlat);
    cudaGetSymbolAddress((void**)&kvb,   g_kv);
    cudaGetSymbolAddress((void**)&attnb, g_attn);

    cudaFuncSetAttribute(attn_kernel,
                         cudaFuncAttributeMaxDynamicSharedMemorySize, ATT_SMEM);

    // Q path: down-proj -> LN -> up-proj
    gemm_mma3<<<dim3(Ll / 128, Mrows / 128), 256>>>(Mrows, Ll, Dm, x, wq_down, bq_down, qlat);
    ln512<<<Mrows, 256>>>(qlat, gq_ln, bq_ln);
    gemm_mma3<<<dim3(Dm / 128, Mrows / 128), 256>>>(Mrows, Dm, Ll, qlat, wq_up, bq_up, qb);

    // KV path: down-proj -> LN -> up-proj (k | v concatenated)
    gemm_mma3<<<dim3(Ll / 128, Mrows / 128), 256>>>(Mrows, Ll, Dm, x, wkv_down, bkv_down, kvlat);
    ln512<<<Mrows, 256>>>(kvlat, gkv_ln, bkv_ln);
    gemm_mma3<<<dim3(2 * Dm / 128, Mrows / 128), 256>>>(Mrows, 2 * Dm, Ll, kvlat, wkv_up, bkv_up, kvb);

    // Causal multi-head attention (flash-style)
    attn_kernel<<<dim3(Sq / 32, Bsz * Hh), 128, ATT_SMEM>>>(qb, kvb, mask, attnb);

    // Output projection
    gemm_mma3<<<dim3(Dm / 128, Mrows / 128), 256>>>(Mrows, Dm, Dm, attnb, w_out, b_out, out);
}

// round 4
// speedup vs baseline: 1.9098x; 1.6215x over previous
#include <cuda_runtime.h>
#include <math_constants.h>
#include <cstdint>

// Problem constants
#define Bsz 2
#define Sq  2048
#define Dm  2048
#define Hh  16
#define Ll  512
#define HDm 128
#define Mrows (Bsz*Sq)      // 4096

// ---------------------------------------------------------------------------
// Scratch (static device globals — no runtime allocation allowed)
// ---------------------------------------------------------------------------
__device__ float g_qlat [(size_t)Mrows * Ll];       //  8 MB
__device__ float g_q    [(size_t)Mrows * Dm];       // 32 MB
__device__ float g_kvlat[(size_t)Mrows * Ll];       //  8 MB
__device__ float g_kv   [(size_t)Mrows * 2 * Dm];   // 64 MB
__device__ float g_attn [(size_t)Mrows * Dm];       // 32 MB

// ---------------------------------------------------------------------------
// Helpers
// ---------------------------------------------------------------------------
__device__ __forceinline__ uint32_t smem_u32(const void* p) {
    uint32_t a;
    asm("{ .reg .u64 t; cvta.to.shared.u64 t, %1; cvt.u32.u64 %0, t; }"
        : "=r"(a) : "l"(p));
    return a;
}
__device__ __forceinline__ void cp16(uint32_t dst, const void* src) {
    asm volatile("cp.async.cg.shared.global [%0], [%1], 16;"
                 :: "r"(dst), "l"(src) : "memory");
}
__device__ __forceinline__ float rna_tf32(float a) {
    float r;
    asm("cvt.rna.tf32.f32 %0, %1;" : "=f"(r) : "f"(a));
    return r;
}
// mma.sync m16n8k8 tf32 (baseline PTX since sm_80 — compiles on sm_103)
__device__ __forceinline__ void mma_tf32(
    float c[4], uint32_t a0, uint32_t a1, uint32_t a2, uint32_t a3,
    uint32_t b0, uint32_t b1)
{
    asm volatile(
        "mma.sync.aligned.m16n8k8.row.col.f32.tf32.tf32.f32 "
        "{%0,%1,%2,%3}, {%4,%5,%6,%7}, {%8,%9}, {%0,%1,%2,%3};"
        : "+f"(c[0]), "+f"(c[1]), "+f"(c[2]), "+f"(c[3])
        : "r"(a0), "r"(a1), "r"(a2), "r"(a3), "r"(b0), "r"(b1));
}

// ---------------------------------------------------------------------------
// 3xTF32 GEMM via mma.sync: C[M,N] = A[M,K] @ W[K,N] + bias[N]  (unchanged)
// ---------------------------------------------------------------------------
#define ASTR 20
#define BSTR 136

__global__ __launch_bounds__(256) void gemm_mma3(
    int M, int N, int K,
    const float* __restrict__ A,
    const float* __restrict__ W,
    const float* __restrict__ bias,
    float* __restrict__ C)
{
    __shared__ __align__(16) float As[2][128 * ASTR];
    __shared__ __align__(16) float Bs[2][16 * BSTR];

    const int tid = threadIdx.x;
    const int wid = tid >> 5, lid = tid & 31;
    const int g = lid >> 2, lq = lid & 3;
    const int m0 = blockIdx.y * 128, n0 = blockIdx.x * 128;
    const int warp_m = (wid & 1) * 64;
    const int warp_n = (wid >> 1) * 32;
    const int nc = K >> 4;

    const uint32_t sA0 = smem_u32(&As[0][0]);
    const uint32_t sB0 = smem_u32(&Bs[0][0]);

    float acc[4][4][4];
    #pragma unroll
    for (int mt = 0; mt < 4; mt++)
        #pragma unroll
        for (int nt = 0; nt < 4; nt++)
            #pragma unroll
            for (int e = 0; e < 4; e++) acc[mt][nt][e] = 0.f;

    auto load_tile = [&](int c, int stg) {
        const int k0 = c << 4;
        const uint32_t sa = sA0 + stg * (128 * ASTR * 4);
        const uint32_t sb = sB0 + stg * (16 * BSTR * 4);
        #pragma unroll
        for (int t = 0; t < 2; t++) {
            int idx = tid + t * 256;
            int m = idx >> 2, k4 = idx & 3;
            cp16(sa + (m * ASTR + k4 * 4) * 4,
                 A + (size_t)(m0 + m) * K + k0 + k4 * 4);
        }
        #pragma unroll
        for (int t = 0; t < 2; t++) {
            int idx = tid + t * 256;
            int k = idx >> 5, nq = idx & 31;
            cp16(sb + (k * BSTR + nq * 4) * 4,
                 W + (size_t)(k0 + k) * N + n0 + nq * 4);
        }
        asm volatile("cp.async.commit_group;" ::: "memory");
    };

    load_tile(0, 0);
    if (nc > 1) load_tile(1, 1);

    for (int c = 0; c < nc; ++c) {
        const int cur = c & 1;
        if (c + 1 < nc) { asm volatile("cp.async.wait_group 1;" ::: "memory"); }
        else            { asm volatile("cp.async.wait_group 0;" ::: "memory"); }
        __syncthreads();

        const float* as = &As[cur][0];
        const float* bs = &Bs[cur][0];

        #pragma unroll
        for (int ks = 0; ks < 2; ks++) {
            const int kb = ks * 8;
            uint32_t Ah[4][4], Al[4][4];
            #pragma unroll
            for (int mt = 0; mt < 4; mt++) {
                const int rbase = warp_m + mt * 16 + g;
                #pragma unroll
                for (int e = 0; e < 4; e++) {
                    const int row = rbase + (e & 1) * 8;
                    const int col = kb + lq + (e >> 1) * 4;
                    float a = as[row * ASTR + col];
                    float h = rna_tf32(a);
                    Ah[mt][e] = __float_as_uint(h);
                    Al[mt][e] = __float_as_uint(rna_tf32(a - h));
                }
            }
            uint32_t Bh[4][2], Bl[4][2];
            #pragma unroll
            for (int nt = 0; nt < 4; nt++) {
                const int nn = warp_n + nt * 8 + g;
                #pragma unroll
                for (int e = 0; e < 2; e++) {
                    const int kk = kb + lq + e * 4;
                    float b = bs[kk * BSTR + nn];
                    float h = rna_tf32(b);
                    Bh[nt][e] = __float_as_uint(h);
                    Bl[nt][e] = __float_as_uint(rna_tf32(b - h));
                }
            }
            #pragma unroll
            for (int mt = 0; mt < 4; mt++)
                #pragma unroll
                for (int nt = 0; nt < 4; nt++) {
                    mma_tf32(acc[mt][nt], Ah[mt][0], Ah[mt][1], Ah[mt][2], Ah[mt][3],
                             Bl[nt][0], Bl[nt][1]);
                    mma_tf32(acc[mt][nt], Al[mt][0], Al[mt][1], Al[mt][2], Al[mt][3],
                             Bh[nt][0], Bh[nt][1]);
                    mma_tf32(acc[mt][nt], Ah[mt][0], Ah[mt][1], Ah[mt][2], Ah[mt][3],
                             Bh[nt][0], Bh[nt][1]);
                }
        }
        __syncthreads();
        if (c + 2 < nc) load_tile(c + 2, cur);
    }

    #pragma unroll
    for (int mt = 0; mt < 4; mt++) {
        const int r0 = m0 + warp_m + mt * 16 + g;
        #pragma unroll
        for (int nt = 0; nt < 4; nt++) {
            const int col = n0 + warp_n + nt * 8 + lq * 2;
            const float2 b2 = *(const float2*)(bias + col);
            float2 o;
            o.x = acc[mt][nt][0] + b2.x;
            o.y = acc[mt][nt][1] + b2.y;
            *(float2*)(C + (size_t)r0 * N + col) = o;
            o.x = acc[mt][nt][2] + b2.x;
            o.y = acc[mt][nt][3] + b2.y;
            *(float2*)(C + (size_t)(r0 + 8) * N + col) = o;
        }
    }
}

// ---------------------------------------------------------------------------
// LayerNorm over last dim (512), in place. One block (256 threads) per row.
// ---------------------------------------------------------------------------
__global__ __launch_bounds__(256) void ln512(
    float* __restrict__ x,
    const float* __restrict__ g,
    const float* __restrict__ b)
{
    const int row = blockIdx.x;
    float* xr = x + (size_t)row * Ll;
    const int tid = threadIdx.x;

    float v0 = xr[tid];
    float v1 = xr[tid + 256];
    float s  = v0 + v1;
    float sq = v0 * v0 + v1 * v1;

    #pragma unroll
    for (int o = 16; o > 0; o >>= 1) {
        s  += __shfl_xor_sync(0xffffffffu, s,  o);
        sq += __shfl_xor_sync(0xffffffffu, sq, o);
    }
    __shared__ float ss[8], ssq[8];
    __shared__ float mean_sh, inv_sh;
    const int w = tid >> 5;
    if ((tid & 31) == 0) { ss[w] = s; ssq[w] = sq; }
    __syncthreads();
    if (tid == 0) {
        float S = 0.f, SQ = 0.f;
        #pragma unroll
        for (int i = 0; i < 8; i++) { S += ss[i]; SQ += ssq[i]; }
        float m = S * (1.f / Ll);
        float var = SQ * (1.f / Ll) - m * m;
        mean_sh = m;
        inv_sh = rsqrtf(var + 1e-5f);
    }
    __syncthreads();
    const float m = mean_sh, inv = inv_sh;
    xr[tid]       = (v0 - m) * inv * g[tid]       + b[tid];
    xr[tid + 256] = (v1 - m) * inv * g[tid + 256] + b[tid + 256];
}

// ---------------------------------------------------------------------------
// Flash attention via mma.sync tf32 (3xTF32), causal + padding mask.
// CTA: 64 queries (4 warps x m16), key tiles of 64, HD=128.
// Double-buffered K/V via cp.async. Per-warp P staging in smem.
// ---------------------------------------------------------------------------
#define QSTR 132
#define KSTR 132
#define VSTR 140
#define PSTR 68
// float offsets
#define AQS_OFF 0
#define AKS_OFF(s) (8448 + (s) * 8448)
#define AVS_OFF(s) (25344 + (s) * 8960)
#define APS_OFF 43264
#define AMASK_BYTE_OFF 190464          // 47616 floats * 4
#define ATT_SMEM (190464 + 128)

__global__ __launch_bounds__(128, 1) void attn_mma(
    const float* __restrict__ q,
    const float* __restrict__ kv,
    const unsigned char* __restrict__ mask,
    float* __restrict__ out)
{
    extern __shared__ float sm[];
    unsigned char* smb = (unsigned char*)sm;

    const int bh = blockIdx.y;
    const int b = bh >> 4, h = bh & 15;
    const int qb = gridDim.x - 1 - blockIdx.x;   // heavy blocks first
    const int q0 = qb * 64;

    const int tid = threadIdx.x;
    const int wid = tid >> 5, lid = tid & 31;
    const int g = lid >> 2, lq = lid & 3;
    const int warp_m = wid * 16;

    const float* Qp = q  + (size_t)b * Sq * Dm       + (size_t)h * HDm;
    const float* Kp = kv + (size_t)b * Sq * (2 * Dm) + (size_t)h * HDm;
    const float* Vp = Kp + Dm;
    const unsigned char* mp = mask + (size_t)b * Sq;

    const uint32_t smu = smem_u32(sm);

    // Q tile 64x128 -> smem
    #pragma unroll
    for (int t = 0; t < 16; t++) {
        int idx = tid + t * 128;
        int row = idx >> 5, c4 = (idx & 31) << 2;
        cp16(smu + (AQS_OFF + row * QSTR + c4) * 4,
             Qp + (size_t)(q0 + row) * Dm + c4);
    }

    auto load_stage = [&](int kt, int s) {
        const int k0 = kt * 64;
        #pragma unroll
        for (int t = 0; t < 16; t++) {
            int idx = tid + t * 128;
            int row = idx >> 5, c4 = (idx & 31) << 2;
            size_t base = (size_t)(k0 + row) * (2 * Dm) + c4;
            cp16(smu + (AKS_OFF(s) + row * KSTR + c4) * 4, Kp + base);
            cp16(smu + (AVS_OFF(s) + row * VSTR + c4) * 4, Vp + base);
        }
        if (tid < 4)
            cp16(smu + AMASK_BYTE_OFF + s * 64 + tid * 16, mp + k0 + tid * 16);
        asm volatile("cp.async.commit_group;" ::: "memory");
    };

    load_stage(0, 0);   // Q rides in this group too

    const int row0 = q0 + warp_m + g;
    const int row1 = row0 + 8;
    float m_i0 = -CUDART_INF_F, m_i1 = -CUDART_INF_F;
    float l0 = 0.f, l1 = 0.f;
    float acc[16][4];
    #pragma unroll
    for (int nt = 0; nt < 16; nt++)
        #pragma unroll
        for (int e = 0; e < 4; e++) acc[nt][e] = 0.f;

    const float scale = 0.08838834764831845f;   // 1/sqrt(128)

    for (int kt = 0; kt <= qb; ++kt) {
        const int st = kt & 1;
        asm volatile("cp.async.wait_group 0;" ::: "memory");
        __syncthreads();
        if (kt < qb) load_stage(kt + 1, st ^ 1);

        const float* qs = sm + AQS_OFF;
        const float* ks = sm + AKS_OFF(st);
        const float* vs = sm + AVS_OFF(st);
        float* psm = sm + APS_OFF;
        const unsigned char* mk = smb + AMASK_BYTE_OFF + st * 64;

        // ---- scores: S = Q @ K^T  (3xTF32) ----
        float sc[8][4];
        #pragma unroll
        for (int nt = 0; nt < 8; nt++)
            #pragma unroll
            for (int e = 0; e < 4; e++) sc[nt][e] = 0.f;

        #pragma unroll 4
        for (int k8 = 0; k8 < 16; k8++) {
            const int kc = k8 * 8;
            uint32_t qh[4], qlo[4];
            #pragma unroll
            for (int e = 0; e < 4; e++) {
                float a = qs[(warp_m + g + (e & 1) * 8) * QSTR + kc + lq + (e >> 1) * 4];
                float hh = rna_tf32(a);
                qh[e]  = __float_as_uint(hh);
                qlo[e] = __float_as_uint(rna_tf32(a - hh));
            }
            #pragma unroll
            for (int nt = 0; nt < 8; nt++) {
                const float* kr = ks + (nt * 8 + g) * KSTR + kc + lq;
                float b0 = kr[0], b1 = kr[4];
                float h0 = rna_tf32(b0), h1 = rna_tf32(b1);
                uint32_t bh0 = __float_as_uint(h0), bh1 = __float_as_uint(h1);
                uint32_t bl0 = __float_as_uint(rna_tf32(b0 - h0));
                uint32_t bl1 = __float_as_uint(rna_tf32(b1 - h1));
                mma_tf32(sc[nt], qh[0], qh[1], qh[2], qh[3], bl0, bl1);
                mma_tf32(sc[nt], qlo[0], qlo[1], qlo[2], qlo[3], bh0, bh1);
                mma_tf32(sc[nt], qh[0], qh[1], qh[2], qh[3], bh0, bh1);
            }
        }

        // ---- mask + scale + row max ----
        const bool diag = (kt == qb);
        float m0 = -CUDART_INF_F, m1 = -CUDART_INF_F;
        #pragma unroll
        for (int nt = 0; nt < 8; nt++) {
            const int cl = nt * 8 + 2 * lq;
            const int cg = kt * 64 + cl;
            const bool pk0 = mk[cl] != 0, pk1 = mk[cl + 1] != 0;
            float v0 = (pk0 || (diag && cg     > row0)) ? -CUDART_INF_F : sc[nt][0] * scale;
            float v1 = (pk1 || (diag && cg + 1 > row0)) ? -CUDART_INF_F : sc[nt][1] * scale;
            float v2 = (pk0 || (diag && cg     > row1)) ? -CUDART_INF_F : sc[nt][2] * scale;
            float v3 = (pk1 || (diag && cg + 1 > row1)) ? -CUDART_INF_F : sc[nt][3] * scale;
            sc[nt][0] = v0; sc[nt][1] = v1; sc[nt][2] = v2; sc[nt][3] = v3;
            m0 = fmaxf(m0, fmaxf(v0, v1));
            m1 = fmaxf(m1, fmaxf(v2, v3));
        }
        m0 = fmaxf(m0, __shfl_xor_sync(0xffffffffu, m0, 1));
        m0 = fmaxf(m0, __shfl_xor_sync(0xffffffffu, m0, 2));
        m1 = fmaxf(m1, __shfl_xor_sync(0xffffffffu, m1, 1));
        m1 = fmaxf(m1, __shfl_xor_sync(0xffffffffu, m1, 2));

        const float mn0 = fmaxf(m_i0, m0), mn1 = fmaxf(m_i1, m1);
        const float corr0 = (mn0 == -CUDART_INF_F) ? 1.f : __expf(m_i0 - mn0);
        const float corr1 = (mn1 == -CUDART_INF_F) ? 1.f : __expf(m_i1 - mn1);
        const float base0 = (mn0 == -CUDART_INF_F) ? 0.f : mn0;
        const float base1 = (mn1 == -CUDART_INF_F) ? 0.f : mn1;

        float psum0 = 0.f, psum1 = 0.f;
        #pragma unroll
        for (int nt = 0; nt < 8; nt++) {
            float p0 = (sc[nt][0] == -CUDART_INF_F) ? 0.f : __expf(sc[nt][0] - base0);
            float p1 = (sc[nt][1] == -CUDART_INF_F) ? 0.f : __expf(sc[nt][1] - base0);
            float p2 = (sc[nt][2] == -CUDART_INF_F) ? 0.f : __expf(sc[nt][2] - base1);
            float p3 = (sc[nt][3] == -CUDART_INF_F) ? 0.f : __expf(sc[nt][3] - base1);
            sc[nt][0] = p0; sc[nt][1] = p1; sc[nt][2] = p2; sc[nt][3] = p3;
            psum0 += p0 + p1;
            psum1 += p2 + p3;
        }
        psum0 += __shfl_xor_sync(0xffffffffu, psum0, 1);
        psum0 += __shfl_xor_sync(0xffffffffu, psum0, 2);
        psum1 += __shfl_xor_sync(0xffffffffu, psum1, 1);
        psum1 += __shfl_xor_sync(0xffffffffu, psum1, 2);
        l0 = l0 * corr0 + psum0;
        l1 = l1 * corr1 + psum1;
        m_i0 = mn0; m_i1 = mn1;

        #pragma unroll
        for (int nt = 0; nt < 16; nt++) {
            acc[nt][0] *= corr0; acc[nt][1] *= corr0;
            acc[nt][2] *= corr1; acc[nt][3] *= corr1;
        }

        // ---- stage P (per-warp private rows) ----
        __syncwarp();
        #pragma unroll
        for (int nt = 0; nt < 8; nt++) {
            const int cl = nt * 8 + 2 * lq;
            *(float2*)&psm[(warp_m + g) * PSTR + cl]     = make_float2(sc[nt][0], sc[nt][1]);
            *(float2*)&psm[(warp_m + g + 8) * PSTR + cl] = make_float2(sc[nt][2], sc[nt][3]);
        }
        __syncwarp();

        // ---- O += P @ V  (3xTF32) ----
        #pragma unroll 2
        for (int k8 = 0; k8 < 8; k8++) {
            const int kc = k8 * 8;
            uint32_t ph[4], plo[4];
            #pragma unroll
            for (int e = 0; e < 4; e++) {
                float a = psm[(warp_m + g + (e & 1) * 8) * PSTR + kc + lq + (e >> 1) * 4];
                float hh = rna_tf32(a);
                ph[e]  = __float_as_uint(hh);
                plo[e] = __float_as_uint(rna_tf32(a - hh));
            }
            #pragma unroll
            for (int nt = 0; nt < 16; nt++) {
                const float* vr = vs + (kc + lq) * VSTR + nt * 8 + g;
                float b0 = vr[0], b1 = vr[4 * VSTR];
                float h0 = rna_tf32(b0), h1 = rna_tf32(b1);
                uint32_t bh0 = __float_as_uint(h0), bh1 = __float_as_uint(h1);
                uint32_t bl0 = __float_as_uint(rna_tf32(b0 - h0));
                uint32_t bl1 = __float_as_uint(rna_tf32(b1 - h1));
                mma_tf32(acc[nt], ph[0], ph[1], ph[2], ph[3], bl0, bl1);
                mma_tf32(acc[nt], plo[0], plo[1], plo[2], plo[3], bh0, bh1);
                mma_tf32(acc[nt], ph[0], ph[1], ph[2], ph[3], bh0, bh1);
            }
        }
        __syncthreads();
    }

    // ---- epilogue ----
    const float inv0 = (l0 > 0.f) ? (1.f / l0) : 0.f;
    const float inv1 = (l1 > 0.f) ? (1.f / l1) : 0.f;
    float* o0 = out + (size_t)(b * Sq + row0) * Dm + (size_t)h * HDm;
    float* o1 = out + (size_t)(b * Sq + row1) * Dm + (size_t)h * HDm;
    #pragma unroll
    for (int nt = 0; nt < 16; nt++) {
        const int cl = nt * 8 + 2 * lq;
        *(float2*)(o0 + cl) = make_float2(acc[nt][0] * inv0, acc[nt][1] * inv0);
        *(float2*)(o1 + cl) = make_float2(acc[nt][2] * inv1, acc[nt][3] * inv1);
    }
}

// ---------------------------------------------------------------------------
// Launch
// ---------------------------------------------------------------------------
extern "C" void kernel_launch(void* const* d_in, const int* in_sizes, int n_in,
                              void* d_out, int out_size)
{
    const float*         x        = (const float*)d_in[0];
    const unsigned char* mask     = (const unsigned char*)d_in[1];
    const float*         wq_down  = (const float*)d_in[2];
    const float*         bq_down  = (const float*)d_in[3];
    const float*         gq_ln    = (const float*)d_in[4];
    const float*         bq_ln    = (const float*)d_in[5];
    const float*         wq_up    = (const float*)d_in[6];
    const float*         bq_up    = (const float*)d_in[7];
    const float*         wkv_down = (const float*)d_in[8];
    const float*         bkv_down = (const float*)d_in[9];
    const float*         gkv_ln   = (const float*)d_in[10];
    const float*         bkv_ln   = (const float*)d_in[11];
    const float*         wkv_up   = (const float*)d_in[12];
    const float*         bkv_up   = (const float*)d_in[13];
    const float*         w_out    = (const float*)d_in[14];
    const float*         b_out    = (const float*)d_in[15];
    float* out = (float*)d_out;

    float *qlat, *qb, *kvlat, *kvb, *attnb;
    cudaGetSymbolAddress((void**)&qlat,  g_qlat);
    cudaGetSymbolAddress((void**)&qb,    g_q);
    cudaGetSymbolAddress((void**)&kvlat, g_kvlat);
    cudaGetSymbolAddress((void**)&kvb,   g_kv);
    cudaGetSymbolAddress((void**)&attnb, g_attn);

    cudaFuncSetAttribute(attn_mma,
                         cudaFuncAttributeMaxDynamicSharedMemorySize, ATT_SMEM);

    // Q path: down-proj -> LN -> up-proj
    gemm_mma3<<<dim3(Ll / 128, Mrows / 128), 256>>>(Mrows, Ll, Dm, x, wq_down, bq_down, qlat);
    ln512<<<Mrows, 256>>>(qlat, gq_ln, bq_ln);
    gemm_mma3<<<dim3(Dm / 128, Mrows / 128), 256>>>(Mrows, Dm, Ll, qlat, wq_up, bq_up, qb);

    // KV path: down-proj -> LN -> up-proj (k | v concatenated)
    gemm_mma3<<<dim3(Ll / 128, Mrows / 128), 256>>>(Mrows, Ll, Dm, x, wkv_down, bkv_down, kvlat);
    ln512<<<Mrows, 256>>>(kvlat, gkv_ln, bkv_ln);
    gemm_mma3<<<dim3(2 * Dm / 128, Mrows / 128), 256>>>(Mrows, 2 * Dm, Ll, kvlat, wkv_up, bkv_up, kvb);

    // Causal multi-head attention (flash, tensor cores)
    attn_mma<<<dim3(Sq / 64, Bsz * Hh), 128, ATT_SMEM>>>(qb, kvb, mask, attnb);

    // Output projection
    gemm_mma3<<<dim3(Dm / 128, Mrows / 128), 256>>>(Mrows, Dm, Dm, attnb, w_out, b_out, out);
}

// round 5
// speedup vs baseline: 1.9188x; 1.0047x over previous
#include <cuda_runtime.h>
#include <math_constants.h>
#include <cstdint>

// Problem constants
#define Bsz 2
#define Sq  2048
#define Dm  2048
#define Hh  16
#define Ll  512
#define HDm 128
#define Mrows (Bsz*Sq)      // 4096

// ---------------------------------------------------------------------------
// Scratch (static device globals — no runtime allocation allowed)
// ---------------------------------------------------------------------------
__device__ float g_qlat [(size_t)Mrows * Ll];       //  8 MB
__device__ float g_q    [(size_t)Mrows * Dm];       // 32 MB
__device__ float g_kvlat[(size_t)Mrows * Ll];       //  8 MB
__device__ float g_kv   [(size_t)Mrows * 2 * Dm];   // 64 MB
__device__ float g_attn [(size_t)Mrows * Dm];       // 32 MB

// ---------------------------------------------------------------------------
// Helpers
// ---------------------------------------------------------------------------
__device__ __forceinline__ uint32_t smem_u32(const void* p) {
    uint32_t a;
    asm("{ .reg .u64 t; cvta.to.shared.u64 t, %1; cvt.u32.u64 %0, t; }"
        : "=r"(a) : "l"(p));
    return a;
}
__device__ __forceinline__ void cp16(uint32_t dst, const void* src) {
    asm volatile("cp.async.cg.shared.global [%0], [%1], 16;"
                 :: "r"(dst), "l"(src) : "memory");
}
__device__ __forceinline__ float rna_tf32(float a) {
    float r;
    asm("cvt.rna.tf32.f32 %0, %1;" : "=f"(r) : "f"(a));
    return r;
}
// mma.sync m16n8k8 tf32 (baseline PTX since sm_80 — compiles on sm_103)
__device__ __forceinline__ void mma_tf32(
    float c[4], uint32_t a0, uint32_t a1, uint32_t a2, uint32_t a3,
    uint32_t b0, uint32_t b1)
{
    asm volatile(
        "mma.sync.aligned.m16n8k8.row.col.f32.tf32.tf32.f32 "
        "{%0,%1,%2,%3}, {%4,%5,%6,%7}, {%8,%9}, {%0,%1,%2,%3};"
        : "+f"(c[0]), "+f"(c[1]), "+f"(c[2]), "+f"(c[3])
        : "r"(a0), "r"(a1), "r"(a2), "r"(a3), "r"(b0), "r"(b1));
}

// ---------------------------------------------------------------------------
// 3xTF32 GEMM via mma.sync: C[M,N] = A[M,K] @ W[K,N] + bias[N]  (unchanged)
// ---------------------------------------------------------------------------
#define ASTR 20
#define BSTR 136

__global__ __launch_bounds__(256) void gemm_mma3(
    int M, int N, int K,
    const float* __restrict__ A,
    const float* __restrict__ W,
    const float* __restrict__ bias,
    float* __restrict__ C)
{
    __shared__ __align__(16) float As[2][128 * ASTR];
    __shared__ __align__(16) float Bs[2][16 * BSTR];

    const int tid = threadIdx.x;
    const int wid = tid >> 5, lid = tid & 31;
    const int g = lid >> 2, lq = lid & 3;
    const int m0 = blockIdx.y * 128, n0 = blockIdx.x * 128;
    const int warp_m = (wid & 1) * 64;
    const int warp_n = (wid >> 1) * 32;
    const int nc = K >> 4;

    const uint32_t sA0 = smem_u32(&As[0][0]);
    const uint32_t sB0 = smem_u32(&Bs[0][0]);

    float acc[4][4][4];
    #pragma unroll
    for (int mt = 0; mt < 4; mt++)
        #pragma unroll
        for (int nt = 0; nt < 4; nt++)
            #pragma unroll
            for (int e = 0; e < 4; e++) acc[mt][nt][e] = 0.f;

    auto load_tile = [&](int c, int stg) {
        const int k0 = c << 4;
        const uint32_t sa = sA0 + stg * (128 * ASTR * 4);
        const uint32_t sb = sB0 + stg * (16 * BSTR * 4);
        #pragma unroll
        for (int t = 0; t < 2; t++) {
            int idx = tid + t * 256;
            int m = idx >> 2, k4 = idx & 3;
            cp16(sa + (m * ASTR + k4 * 4) * 4,
                 A + (size_t)(m0 + m) * K + k0 + k4 * 4);
        }
        #pragma unroll
        for (int t = 0; t < 2; t++) {
            int idx = tid + t * 256;
            int k = idx >> 5, nq = idx & 31;
            cp16(sb + (k * BSTR + nq * 4) * 4,
                 W + (size_t)(k0 + k) * N + n0 + nq * 4);
        }
        asm volatile("cp.async.commit_group;" ::: "memory");
    };

    load_tile(0, 0);
    if (nc > 1) load_tile(1, 1);

    for (int c = 0; c < nc; ++c) {
        const int cur = c & 1;
        if (c + 1 < nc) { asm volatile("cp.async.wait_group 1;" ::: "memory"); }
        else            { asm volatile("cp.async.wait_group 0;" ::: "memory"); }
        __syncthreads();

        const float* as = &As[cur][0];
        const float* bs = &Bs[cur][0];

        #pragma unroll
        for (int ks = 0; ks < 2; ks++) {
            const int kb = ks * 8;
            uint32_t Ah[4][4], Al[4][4];
            #pragma unroll
            for (int mt = 0; mt < 4; mt++) {
                const int rbase = warp_m + mt * 16 + g;
                #pragma unroll
                for (int e = 0; e < 4; e++) {
                    const int row = rbase + (e & 1) * 8;
                    const int col = kb + lq + (e >> 1) * 4;
                    float a = as[row * ASTR + col];
                    float h = rna_tf32(a);
                    Ah[mt][e] = __float_as_uint(h);
                    Al[mt][e] = __float_as_uint(rna_tf32(a - h));
                }
            }
            uint32_t Bh[4][2], Bl[4][2];
            #pragma unroll
            for (int nt = 0; nt < 4; nt++) {
                const int nn = warp_n + nt * 8 + g;
                #pragma unroll
                for (int e = 0; e < 2; e++) {
                    const int kk = kb + lq + e * 4;
                    float b = bs[kk * BSTR + nn];
                    float h = rna_tf32(b);
                    Bh[nt][e] = __float_as_uint(h);
                    Bl[nt][e] = __float_as_uint(rna_tf32(b - h));
                }
            }
            #pragma unroll
            for (int mt = 0; mt < 4; mt++)
                #pragma unroll
                for (int nt = 0; nt < 4; nt++) {
                    mma_tf32(acc[mt][nt], Ah[mt][0], Ah[mt][1], Ah[mt][2], Ah[mt][3],
                             Bl[nt][0], Bl[nt][1]);
                    mma_tf32(acc[mt][nt], Al[mt][0], Al[mt][1], Al[mt][2], Al[mt][3],
                             Bh[nt][0], Bh[nt][1]);
                    mma_tf32(acc[mt][nt], Ah[mt][0], Ah[mt][1], Ah[mt][2], Ah[mt][3],
                             Bh[nt][0], Bh[nt][1]);
                }
        }
        __syncthreads();
        if (c + 2 < nc) load_tile(c + 2, cur);
    }

    #pragma unroll
    for (int mt = 0; mt < 4; mt++) {
        const int r0 = m0 + warp_m + mt * 16 + g;
        #pragma unroll
        for (int nt = 0; nt < 4; nt++) {
            const int col = n0 + warp_n + nt * 8 + lq * 2;
            const float2 b2 = *(const float2*)(bias + col);
            float2 o;
            o.x = acc[mt][nt][0] + b2.x;
            o.y = acc[mt][nt][1] + b2.y;
            *(float2*)(C + (size_t)r0 * N + col) = o;
            o.x = acc[mt][nt][2] + b2.x;
            o.y = acc[mt][nt][3] + b2.y;
            *(float2*)(C + (size_t)(r0 + 8) * N + col) = o;
        }
    }
}

// ---------------------------------------------------------------------------
// LayerNorm over last dim (512), in place. One block (256 threads) per row.
// ---------------------------------------------------------------------------
__global__ __launch_bounds__(256) void ln512(
    float* __restrict__ x,
    const float* __restrict__ g,
    const float* __restrict__ b)
{
    const int row = blockIdx.x;
    float* xr = x + (size_t)row * Ll;
    const int tid = threadIdx.x;

    float v0 = xr[tid];
    float v1 = xr[tid + 256];
    float s  = v0 + v1;
    float sq = v0 * v0 + v1 * v1;

    #pragma unroll
    for (int o = 16; o > 0; o >>= 1) {
        s  += __shfl_xor_sync(0xffffffffu, s,  o);
        sq += __shfl_xor_sync(0xffffffffu, sq, o);
    }
    __shared__ float ss[8], ssq[8];
    __shared__ float mean_sh, inv_sh;
    const int w = tid >> 5;
    if ((tid & 31) == 0) { ss[w] = s; ssq[w] = sq; }
    __syncthreads();
    if (tid == 0) {
        float S = 0.f, SQ = 0.f;
        #pragma unroll
        for (int i = 0; i < 8; i++) { S += ss[i]; SQ += ssq[i]; }
        float m = S * (1.f / Ll);
        float var = SQ * (1.f / Ll) - m * m;
        mean_sh = m;
        inv_sh = rsqrtf(var + 1e-5f);
    }
    __syncthreads();
    const float m = mean_sh, inv = inv_sh;
    xr[tid]       = (v0 - m) * inv * g[tid]       + b[tid];
    xr[tid + 256] = (v1 - m) * inv * g[tid + 256] + b[tid + 256];
}

// ---------------------------------------------------------------------------
// Flash attention via mma.sync tf32 (3xTF32), causal + padding mask.
// CTA: 128 queries (8 warps x m16), key tiles of 64, HD=128.
// Q held in registers (staged once through the K buffers).
// K/V double-buffered via cp.async. Per-warp P staging in smem.
// ---------------------------------------------------------------------------
#define KSTR 132
#define VSTR 136
#define PSTR 68
// float offsets
#define AKS_OFF(s) ((s) * 8448)             // 2 x 64x132
#define AVS_OFF(s) (16896 + (s) * 8704)     // 2 x 64x136
#define APS_OFF 34304                       // 128x68
#define AMASK_BYTE_OFF 172032               // 43008 floats * 4
#define ATT_SMEM (172032 + 128)

__global__ __launch_bounds__(256, 1) void attn_mma(
    const float* __restrict__ q,
    const float* __restrict__ kv,
    const unsigned char* __restrict__ mask,
    float* __restrict__ out)
{
    extern __shared__ float sm[];
    unsigned char* smb = (unsigned char*)sm;

    const int bh = blockIdx.y;
    const int b = bh >> 4, h = bh & 15;
    const int qb = gridDim.x - 1 - blockIdx.x;   // heavy blocks first
    const int q0 = qb * 128;
    const int ktmax = 2 * qb + 1;                // last key tile (inclusive)

    const int tid = threadIdx.x;
    const int wid = tid >> 5, lid = tid & 31;
    const int g = lid >> 2, lq = lid & 3;
    const int warp_m = wid * 16;

    const float* Qp = q  + (size_t)b * Sq * Dm       + (size_t)h * HDm;
    const float* Kp = kv + (size_t)b * Sq * (2 * Dm) + (size_t)h * HDm;
    const float* Vp = Kp + Dm;
    const unsigned char* mp = mask + (size_t)b * Sq;

    const uint32_t smu = smem_u32(sm);

    // ---- stage Q (128x128) through the K buffers, then pull to registers ----
    #pragma unroll
    for (int t = 0; t < 16; t++) {
        int idx = tid + t * 256;
        int row = idx >> 5, c4 = (idx & 31) << 2;
        cp16(smu + (row * KSTR + c4) * 4, Qp + (size_t)(q0 + row) * Dm + c4);
    }
    asm volatile("cp.async.commit_group;" ::: "memory");
    asm volatile("cp.async.wait_group 0;" ::: "memory");
    __syncthreads();

    float Qr[16][4];
    #pragma unroll
    for (int c = 0; c < 16; c++)
        #pragma unroll
        for (int e = 0; e < 4; e++)
            Qr[c][e] = sm[(warp_m + g + (e & 1) * 8) * KSTR + c * 8 + lq + (e >> 1) * 4];
    __syncthreads();

    auto load_stage = [&](int kt, int s) {
        const int k0 = kt * 64;
        #pragma unroll
        for (int t = 0; t < 8; t++) {
            int idx = tid + t * 256;
            int row = idx >> 5, c4 = (idx & 31) << 2;
            size_t base = (size_t)(k0 + row) * (2 * Dm) + c4;
            cp16(smu + (AKS_OFF(s) + row * KSTR + c4) * 4, Kp + base);
            cp16(smu + (AVS_OFF(s) + row * VSTR + c4) * 4, Vp + base);
        }
        if (tid < 4)
            cp16(smu + AMASK_BYTE_OFF + s * 64 + tid * 16, mp + k0 + tid * 16);
        asm volatile("cp.async.commit_group;" ::: "memory");
    };

    load_stage(0, 0);

    const int row0 = q0 + warp_m + g;
    const int row1 = row0 + 8;
    float m_i0 = -CUDART_INF_F, m_i1 = -CUDART_INF_F;
    float l0 = 0.f, l1 = 0.f;
    float acc[16][4];
    #pragma unroll
    for (int nt = 0; nt < 16; nt++)
        #pragma unroll
        for (int e = 0; e < 4; e++) acc[nt][e] = 0.f;

    const float scale = 0.08838834764831845f;   // 1/sqrt(128)

    for (int kt = 0; kt <= ktmax; ++kt) {
        const int st = kt & 1;
        asm volatile("cp.async.wait_group 0;" ::: "memory");
        __syncthreads();
        if (kt < ktmax) load_stage(kt + 1, st ^ 1);

        const float* ks = sm + AKS_OFF(st);
        const float* vs = sm + AVS_OFF(st);
        float* psm = sm + APS_OFF;
        const unsigned char* mk = smb + AMASK_BYTE_OFF + st * 64;

        // ---- scores: S = Q @ K^T  (3xTF32) ----
        float sc[8][4];
        #pragma unroll
        for (int nt = 0; nt < 8; nt++)
            #pragma unroll
            for (int e = 0; e < 4; e++) sc[nt][e] = 0.f;

        #pragma unroll 4
        for (int k8 = 0; k8 < 16; k8++) {
            const int kc = k8 * 8;
            uint32_t qh[4], qlo[4];
            #pragma unroll
            for (int e = 0; e < 4; e++) {
                float a = Qr[k8][e];
                float hh = rna_tf32(a);
                qh[e]  = __float_as_uint(hh);
                qlo[e] = __float_as_uint(rna_tf32(a - hh));
            }
            #pragma unroll
            for (int nt = 0; nt < 8; nt++) {
                const float* kr = ks + (nt * 8 + g) * KSTR + kc + lq;
                float b0 = kr[0], b1 = kr[4];
                float h0 = rna_tf32(b0), h1 = rna_tf32(b1);
                uint32_t bh0 = __float_as_uint(h0), bh1 = __float_as_uint(h1);
                uint32_t bl0 = __float_as_uint(rna_tf32(b0 - h0));
                uint32_t bl1 = __float_as_uint(rna_tf32(b1 - h1));
                mma_tf32(sc[nt], qh[0], qh[1], qh[2], qh[3], bl0, bl1);
                mma_tf32(sc[nt], qlo[0], qlo[1], qlo[2], qlo[3], bh0, bh1);
                mma_tf32(sc[nt], qh[0], qh[1], qh[2], qh[3], bh0, bh1);
            }
        }

        // ---- mask + scale + row max ----
        const bool diag = (kt >= 2 * qb);
        float m0 = -CUDART_INF_F, m1 = -CUDART_INF_F;
        #pragma unroll
        for (int nt = 0; nt < 8; nt++) {
            const int cl = nt * 8 + 2 * lq;
            const int cg = kt * 64 + cl;
            const bool pk0 = mk[cl] != 0, pk1 = mk[cl + 1] != 0;
            float v0 = (pk0 || (diag && cg     > row0)) ? -CUDART_INF_F : sc[nt][0] * scale;
            float v1 = (pk1 || (diag && cg + 1 > row0)) ? -CUDART_INF_F : sc[nt][1] * scale;
            float v2 = (pk0 || (diag && cg     > row1)) ? -CUDART_INF_F : sc[nt][2] * scale;
            float v3 = (pk1 || (diag && cg + 1 > row1)) ? -CUDART_INF_F : sc[nt][3] * scale;
            sc[nt][0] = v0; sc[nt][1] = v1; sc[nt][2] = v2; sc[nt][3] = v3;
            m0 = fmaxf(m0, fmaxf(v0, v1));
            m1 = fmaxf(m1, fmaxf(v2, v3));
        }
        m0 = fmaxf(m0, __shfl_xor_sync(0xffffffffu, m0, 1));
        m0 = fmaxf(m0, __shfl_xor_sync(0xffffffffu, m0, 2));
        m1 = fmaxf(m1, __shfl_xor_sync(0xffffffffu, m1, 1));
        m1 = fmaxf(m1, __shfl_xor_sync(0xffffffffu, m1, 2));

        const float mn0 = fmaxf(m_i0, m0), mn1 = fmaxf(m_i1, m1);
        const float corr0 = (mn0 == -CUDART_INF_F) ? 1.f : __expf(m_i0 - mn0);
        const float corr1 = (mn1 == -CUDART_INF_F) ? 1.f : __expf(m_i1 - mn1);
        const float base0 = (mn0 == -CUDART_INF_F) ? 0.f : mn0;
        const float base1 = (mn1 == -CUDART_INF_F) ? 0.f : mn1;

        float psum0 = 0.f, psum1 = 0.f;
        #pragma unroll
        for (int nt = 0; nt < 8; nt++) {
            float p0 = (sc[nt][0] == -CUDART_INF_F) ? 0.f : __expf(sc[nt][0] - base0);
            float p1 = (sc[nt][1] == -CUDART_INF_F) ? 0.f : __expf(sc[nt][1] - base0);
            float p2 = (sc[nt][2] == -CUDART_INF_F) ? 0.f : __expf(sc[nt][2] - base1);
            float p3 = (sc[nt][3] == -CUDART_INF_F) ? 0.f : __expf(sc[nt][3] - base1);
            sc[nt][0] = p0; sc[nt][1] = p1; sc[nt][2] = p2; sc[nt][3] = p3;
            psum0 += p0 + p1;
            psum1 += p2 + p3;
        }
        psum0 += __shfl_xor_sync(0xffffffffu, psum0, 1);
        psum0 += __shfl_xor_sync(0xffffffffu, psum0, 2);
        psum1 += __shfl_xor_sync(0xffffffffu, psum1, 1);
        psum1 += __shfl_xor_sync(0xffffffffu, psum1, 2);
        l0 = l0 * corr0 + psum0;
        l1 = l1 * corr1 + psum1;
        m_i0 = mn0; m_i1 = mn1;

        #pragma unroll
        for (int nt = 0; nt < 16; nt++) {
            acc[nt][0] *= corr0; acc[nt][1] *= corr0;
            acc[nt][2] *= corr1; acc[nt][3] *= corr1;
        }

        // ---- stage P (per-warp private rows) ----
        __syncwarp();
        #pragma unroll
        for (int nt = 0; nt < 8; nt++) {
            const int cl = nt * 8 + 2 * lq;
            *(float2*)&psm[(warp_m + g) * PSTR + cl]     = make_float2(sc[nt][0], sc[nt][1]);
            *(float2*)&psm[(warp_m + g + 8) * PSTR + cl] = make_float2(sc[nt][2], sc[nt][3]);
        }
        __syncwarp();

        // ---- O += P @ V  (3xTF32) ----
        #pragma unroll 2
        for (int k8 = 0; k8 < 8; k8++) {
            const int kc = k8 * 8;
            uint32_t ph[4], plo[4];
            #pragma unroll
            for (int e = 0; e < 4; e++) {
                float a = psm[(warp_m + g + (e & 1) * 8) * PSTR + kc + lq + (e >> 1) * 4];
                float hh = rna_tf32(a);
                ph[e]  = __float_as_uint(hh);
                plo[e] = __float_as_uint(rna_tf32(a - hh));
            }
            #pragma unroll
            for (int nt = 0; nt < 16; nt++) {
                const float* vr = vs + (kc + lq) * VSTR + nt * 8 + g;
                float b0 = vr[0], b1 = vr[4 * VSTR];
                float h0 = rna_tf32(b0), h1 = rna_tf32(b1);
                uint32_t bh0 = __float_as_uint(h0), bh1 = __float_as_uint(h1);
                uint32_t bl0 = __float_as_uint(rna_tf32(b0 - h0));
                uint32_t bl1 = __float_as_uint(rna_tf32(b1 - h1));
                mma_tf32(acc[nt], ph[0], ph[1], ph[2], ph[3], bl0, bl1);
                mma_tf32(acc[nt], plo[0], plo[1], plo[2], plo[3], bh0, bh1);
                mma_tf32(acc[nt], ph[0], ph[1], ph[2], ph[3], bh0, bh1);
            }
        }
        __syncthreads();
    }

    // ---- epilogue ----
    const float inv0 = (l0 > 0.f) ? (1.f / l0) : 0.f;
    const float inv1 = (l1 > 0.f) ? (1.f / l1) : 0.f;
    float* o0 = out + (size_t)(b * Sq + row0) * Dm + (size_t)h * HDm;
    float* o1 = out + (size_t)(b * Sq + row1) * Dm + (size_t)h * HDm;
    #pragma unroll
    for (int nt = 0; nt < 16; nt++) {
        const int cl = nt * 8 + 2 * lq;
        *(float2*)(o0 + cl) = make_float2(acc[nt][0] * inv0, acc[nt][1] * inv0);
        *(float2*)(o1 + cl) = make_float2(acc[nt][2] * inv1, acc[nt][3] * inv1);
    }
}

// ---------------------------------------------------------------------------
// Launch
// ---------------------------------------------------------------------------
extern "C" void kernel_launch(void* const* d_in, const int* in_sizes, int n_in,
                              void* d_out, int out_size)
{
    const float*         x        = (const float*)d_in[0];
    const unsigned char* mask     = (const unsigned char*)d_in[1];
    const float*         wq_down  = (const float*)d_in[2];
    const float*         bq_down  = (const float*)d_in[3];
    const float*         gq_ln    = (const float*)d_in[4];
    const float*         bq_ln    = (const float*)d_in[5];
    const float*         wq_up    = (const float*)d_in[6];
    const float*         bq_up    = (const float*)d_in[7];
    const float*         wkv_down = (const float*)d_in[8];
    const float*         bkv_down = (const float*)d_in[9];
    const float*         gkv_ln   = (const float*)d_in[10];
    const float*         bkv_ln   = (const float*)d_in[11];
    const float*         wkv_up   = (const float*)d_in[12];
    const float*         bkv_up   = (const float*)d_in[13];
    const float*         w_out    = (const float*)d_in[14];
    const float*         b_out    = (const float*)d_in[15];
    float* out = (float*)d_out;

    float *qlat, *qb, *kvlat, *kvb, *attnb;
    cudaGetSymbolAddress((void**)&qlat,  g_qlat);
    cudaGetSymbolAddress((void**)&qb,    g_q);
    cudaGetSymbolAddress((void**)&kvlat, g_kvlat);
    cudaGetSymbolAddress((void**)&kvb,   g_kv);
    cudaGetSymbolAddress((void**)&attnb, g_attn);

    cudaFuncSetAttribute(attn_mma,
                         cudaFuncAttributeMaxDynamicSharedMemorySize, ATT_SMEM);

    // Q path: down-proj -> LN -> up-proj
    gemm_mma3<<<dim3(Ll / 128, Mrows / 128), 256>>>(Mrows, Ll, Dm, x, wq_down, bq_down, qlat);
    ln512<<<Mrows, 256>>>(qlat, gq_ln, bq_ln);
    gemm_mma3<<<dim3(Dm / 128, Mrows / 128), 256>>>(Mrows, Dm, Ll, qlat, wq_up, bq_up, qb);

    // KV path: down-proj -> LN -> up-proj (k | v concatenated)
    gemm_mma3<<<dim3(Ll / 128, Mrows / 128), 256>>>(Mrows, Ll, Dm, x, wkv_down, bkv_down, kvlat);
    ln512<<<Mrows, 256>>>(kvlat, gkv_ln, bkv_ln);
    gemm_mma3<<<dim3(2 * Dm / 128, Mrows / 128), 256>>>(Mrows, 2 * Dm, Ll, kvlat, wkv_up, bkv_up, kvb);

    // Causal multi-head attention (flash, tensor cores, 128q x 8 warps)
    attn_mma<<<dim3(Sq / 128, Bsz * Hh), 256, ATT_SMEM>>>(qb, kvb, mask, attnb);

    // Output projection
    gemm_mma3<<<dim3(Dm / 128, Mrows / 128), 256>>>(Mrows, Dm, Dm, attnb, w_out, b_out, out);
}